// round 5
// baseline (speedup 1.0000x reference)
#include <cuda_runtime.h>
#include <cuda_bf16.h>

#define DIM 128
#define MAX_TYP 4096

// Scratch: circular-window sums of updated type rows, and the structure flag.
__device__ float g_W[MAX_TYP * DIM];   // 2 MB static scratch (allowed)
__device__ int   g_flag;

// ---------------------------------------------------------------------------
__global__ void init_flag_kernel(int ok) { g_flag = ok; }

// Verify: sub3_row[c*deg3 + j] == (sub3_row[c*deg3] + j) mod n_typ  for all c,j.
// Any violation clears the flag (benign race, all writers write 0).
__global__ void check_kernel(const int* __restrict__ sub3_row,
                             int n_ent, int n_typ, int deg3) {
    const int c = blockIdx.x * blockDim.x + threadIdx.x;
    if (c >= n_ent) return;
    const int* r = sub3_row + (size_t)c * deg3;
    const int base = __ldg(r);
    bool ok = (base >= 0) && (base < n_typ);
    for (int j = 1; j < deg3; ++j) {
        int expect = base + j;
        if (expect >= n_typ) expect -= n_typ;
        ok = ok && (__ldg(r + j) == expect);
    }
    if (!ok) g_flag = 0;
}

// ---------------------------------------------------------------------------
// Kernel A (sub2): one block (256 thr = 8 warps) per type node c.
//   out[rc] = emb[rc] + sum_j emb[left_specific[sub2_row[...]]] + (n_ent-deg2)
// ---------------------------------------------------------------------------
__global__ void sub2_kernel(const float* __restrict__ emb,
                            const int* __restrict__ sub2_row,
                            const int* __restrict__ left_specific,
                            const int* __restrict__ right_common,
                            float* __restrict__ out,
                            int n_ent, int deg2) {
    extern __shared__ char smem_raw[];
    int*    rows = (int*)smem_raw;                                  // [deg2]
    float4* red  = (float4*)(smem_raw + ((deg2 * 4 + 127) & ~127)); // [8][32]

    const int c     = blockIdx.x;
    const int w     = threadIdx.x >> 5;
    const int lane  = threadIdx.x & 31;
    const int nwarp = blockDim.x >> 5;

    for (int j = threadIdx.x; j < deg2; j += blockDim.x)
        rows[j] = left_specific[__ldg(sub2_row + (size_t)c * deg2 + j)];
    __syncthreads();

    float4 acc = make_float4(0.f, 0.f, 0.f, 0.f);
    for (int j = w; j < deg2; j += nwarp) {
        const float4 v = __ldg((const float4*)(emb + (size_t)rows[j] * DIM) + lane);
        acc.x += v.x; acc.y += v.y; acc.z += v.z; acc.w += v.w;
    }
    red[w * 32 + lane] = acc;
    __syncthreads();

    if (w == 0) {
        float4 s = red[lane];
#pragma unroll
        for (int k = 1; k < 8; ++k) {
            const float4 v = red[k * 32 + lane];
            s.x += v.x; s.y += v.y; s.z += v.z; s.w += v.w;
        }
        const int   rc = right_common[c];
        const float a  = (float)(n_ent - deg2);
        const float4 e = __ldg((const float4*)(emb + (size_t)rc * DIM) + lane);
        float4 r;
        r.x = e.x + s.x + a; r.y = e.y + s.y + a;
        r.z = e.z + s.z + a; r.w = e.w + s.w + a;
        ((float4*)(out + (size_t)rc * DIM) + lane)[0] = r;
    }
}

// ---------------------------------------------------------------------------
// Window precompute: W[t] = sum_{j<deg3} out[left_common[(t+j) mod n_typ]].
// Reads only the (L2-resident) updated type rows. Runs after sub2.
// ---------------------------------------------------------------------------
__global__ void window_kernel(const float* __restrict__ out,
                              const int* __restrict__ left_common,
                              int n_typ, int deg3) {
    const int t = blockIdx.x;
    const int d = threadIdx.x;
    float acc = 0.0f;
    for (int j = 0; j < deg3; ++j) {
        int tt = t + j;
        if (tt >= n_typ) tt -= n_typ;
        acc += __ldg(out + (size_t)__ldg(left_common + tt) * DIM + d);
    }
    g_W[(size_t)t * DIM + d] = acc;
}

// ---------------------------------------------------------------------------
// Kernel B (sub3): each warp processes 8 entities. Fast path (g_flag): one
// W-gather per entity. Fallback: deg3 type-row gathers per entity.
//   out[rs] = emb[rs] * (1 - (sum_type_rows + (n_typ-deg3)) / (1+deg3))
// ---------------------------------------------------------------------------
__global__ void sub3_kernel(const float* __restrict__ emb,
                            const int* __restrict__ sub3_row,
                            const int* __restrict__ left_common,
                            const int* __restrict__ right_specific,
                            float* out,
                            int n_ent, int n_typ, int deg3) {
    const int wpb  = blockDim.x >> 5;
    const int gw   = blockIdx.x * wpb + (threadIdx.x >> 5);
    const int lane = threadIdx.x & 31;
    const int base = gw * 8;
    if (base >= n_ent) return;

    const float addc = (float)(n_typ - deg3);
    const float inv  = 1.0f / (float)(1 + deg3);

    if (g_flag) {
        // --- fast path: single window-sum gather per entity ---
        int t_l = 0, rs_l = 0;
        if (lane < 8 && base + lane < n_ent)
            t_l = __ldg(sub3_row + (size_t)(base + lane) * deg3);     // window start
        if (lane >= 8 && lane < 16 && base + (lane - 8) < n_ent)
            rs_l = __ldg(right_specific + base + (lane - 8));

        int    rs[8];
        float4 ev[8], wv[8];
#pragma unroll
        for (int e = 0; e < 8; ++e) {
            rs[e] = __shfl_sync(0xffffffffu, rs_l, 8 + e);
            if (base + e < n_ent)
                ev[e] = __ldcs((const float4*)(emb + (size_t)rs[e] * DIM) + lane);
        }
#pragma unroll
        for (int e = 0; e < 8; ++e) {
            const int t = __shfl_sync(0xffffffffu, t_l, e);
            if (base + e < n_ent)
                wv[e] = *((const float4*)(g_W + (size_t)t * DIM) + lane);
        }
#pragma unroll
        for (int e = 0; e < 8; ++e) {
            if (base + e >= n_ent) break;
            float4 r;
            r.x = ev[e].x * (1.0f - (wv[e].x + addc) * inv);
            r.y = ev[e].y * (1.0f - (wv[e].y + addc) * inv);
            r.z = ev[e].z * (1.0f - (wv[e].z + addc) * inv);
            r.w = ev[e].w * (1.0f - (wv[e].w + addc) * inv);
            __stcs((float4*)(out + (size_t)rs[e] * DIM) + lane, r);
        }
    } else {
        // --- fallback: per-entity deg3 gathers of updated type rows ---
        for (int e = 0; e < 8; ++e) {
            const int c = base + e;
            if (c >= n_ent) break;
            float4 acc = make_float4(0.f, 0.f, 0.f, 0.f);
            for (int j = 0; j < deg3; ++j) {
                const int node = __ldg(left_common + __ldg(sub3_row + (size_t)c * deg3 + j));
                const float4 v = __ldg((const float4*)(out + (size_t)node * DIM) + lane);
                acc.x += v.x; acc.y += v.y; acc.z += v.z; acc.w += v.w;
            }
            const int   rsc = __ldg(right_specific + c);
            const float4 e4 = __ldcs((const float4*)(emb + (size_t)rsc * DIM) + lane);
            float4 r;
            r.x = e4.x * (1.0f - (acc.x + addc) * inv);
            r.y = e4.y * (1.0f - (acc.y + addc) * inv);
            r.z = e4.z * (1.0f - (acc.z + addc) * inv);
            r.w = e4.w * (1.0f - (acc.w + addc) * inv);
            __stcs((float4*)(out + (size_t)rsc * DIM) + lane, r);
        }
    }
}

extern "C" void kernel_launch(void* const* d_in, const int* in_sizes, int n_in,
                              void* d_out, int out_size) {
    const float* emb            = (const float*)d_in[0];
    const int*   sub2_row       = (const int*)d_in[1];
    const int*   sub3_row       = (const int*)d_in[3];
    const int*   left_specific  = (const int*)d_in[5];
    const int*   right_common   = (const int*)d_in[6];
    const int*   left_common    = (const int*)d_in[7];
    const int*   right_specific = (const int*)d_in[8];
    float*       out            = (float*)d_out;

    const int n_ent = in_sizes[5];                 // 200000
    const int n_typ = in_sizes[7];                 // 1000
    const int deg2  = in_sizes[1] / n_typ;         // 64
    const int deg3  = in_sizes[3] / n_ent;         // 4

    const int shape_ok = (n_typ <= MAX_TYP) ? 1 : 0;

    // Flag init + structure check (independent of sub2).
    init_flag_kernel<<<1, 1>>>(shape_ok);
    check_kernel<<<(n_ent + 255) / 256, 256>>>(sub3_row, n_ent, n_typ, deg3);

    // Phase 1: updated type rows -> out[type rows]
    const int smem = ((deg2 * 4 + 127) & ~127) + 8 * 32 * (int)sizeof(float4);
    sub2_kernel<<<n_typ, 256, smem>>>(
        emb, sub2_row, left_specific, right_common, out, n_ent, deg2);

    // Window sums over updated type rows (needs sub2's output).
    if (shape_ok)
        window_kernel<<<n_typ, DIM>>>(out, left_common, n_typ, deg3);

    // Phase 2: updated entity rows.
    const int wpb = 8;                              // 256 threads
    const int ent_per_block = wpb * 8;              // 8 entities per warp
    const int blocks = (n_ent + ent_per_block - 1) / ent_per_block;
    sub3_kernel<<<blocks, wpb * 32>>>(
        emb, sub3_row, left_common, right_specific, out, n_ent, n_typ, deg3);
}